// round 2
// baseline (speedup 1.0000x reference)
#include <cuda_runtime.h>
#include <cstdint>

// ---------------------------------------------------------------------------
// Int8Linear: per-token dynamic quant -> int8 GEMM (IMMA mma.sync) -> dequant
//   x:             [T, 4096] fp32
//   weight:        [4096, 4096] int8 values, but harness likely delivers int32
//   weight_scales: [4096] fp32
//   bias:          [4096] fp32 (zeros)
//   out:           [T, 4096] fp32
// ---------------------------------------------------------------------------

#define K_DIM 4096
#define N_DIM 4096
#define MAX_T 8192

#define BM 128
#define BN 128
#define BK 64
#define SSTRIDE 80   // 64B row padded to 80B -> conflict-free 4B frag loads

// scratch (allocation-free rule: device globals)
__device__ int8_t g_qx[(size_t)MAX_T * K_DIM];
__device__ float  g_xscale[MAX_T];
__device__ int8_t g_w8[(size_t)N_DIM * K_DIM];
__device__ int    g_w_is_int32;

// ---------------------------------------------------------------------------
// Detect weight dtype: if the buffer holds int32 values (all small ints),
// the first 64 words are in [-200, 200]. If it's raw int8, a word is 4 packed
// random bytes -> virtually never small. Deterministic for fixed input.
// ---------------------------------------------------------------------------
__global__ void detect_kernel(const int* __restrict__ w) {
    if (threadIdx.x == 0 && blockIdx.x == 0) {
        int ok = 1;
#pragma unroll
        for (int i = 0; i < 64; ++i) {
            int v = w[i];
            if (v < -200 || v > 200) ok = 0;
        }
        g_w_is_int32 = ok;
    }
}

// Pack weight into contiguous int8. Each thread emits 4 int8 (one u32).
__global__ void pack_kernel(const void* __restrict__ w) {
    const size_t idx = (size_t)blockIdx.x * blockDim.x + threadIdx.x;  // u32 index
    uint32_t* dst = reinterpret_cast<uint32_t*>(g_w8);
    if (g_w_is_int32) {
        const int4 v = reinterpret_cast<const int4*>(w)[idx];
        uint32_t p = ((uint32_t)(uint8_t)(int8_t)v.x)
                   | ((uint32_t)(uint8_t)(int8_t)v.y << 8)
                   | ((uint32_t)(uint8_t)(int8_t)v.z << 16)
                   | ((uint32_t)(uint8_t)(int8_t)v.w << 24);
        dst[idx] = p;
    } else {
        dst[idx] = reinterpret_cast<const uint32_t*>(w)[idx];
    }
}

// ---------------------------------------------------------------------------
// Quantize: one block per token row. absmax -> scale -> int8, packed u32.
// Matches reference bit-exactly: scale = absmax/127; q = rint(x/scale) clip.
// ---------------------------------------------------------------------------
__global__ void quant_kernel(const float* __restrict__ x) {
    const int row = blockIdx.x;
    const int t   = threadIdx.x;
    const float* xr = x + (size_t)row * K_DIM;

    float4 v[4];
    float amax = 0.f;
#pragma unroll
    for (int i = 0; i < 4; ++i) {
        v[i] = reinterpret_cast<const float4*>(xr)[t + i * 256];
        amax = fmaxf(amax, fmaxf(fmaxf(fabsf(v[i].x), fabsf(v[i].y)),
                                 fmaxf(fabsf(v[i].z), fabsf(v[i].w))));
    }

    __shared__ float smax[8];
#pragma unroll
    for (int o = 16; o > 0; o >>= 1)
        amax = fmaxf(amax, __shfl_xor_sync(0xffffffffu, amax, o));
    if ((t & 31) == 0) smax[t >> 5] = amax;
    __syncthreads();
    if (t < 32) {
        float m = (t < 8) ? smax[t] : 0.f;
#pragma unroll
        for (int o = 4; o > 0; o >>= 1)
            m = fmaxf(m, __shfl_xor_sync(0xffffffffu, m, o));
        if (t == 0) smax[0] = m;
    }
    __syncthreads();

    const float scale = smax[0] / 127.0f;
    if (t == 0) g_xscale[row] = scale;
    const float sdiv = (scale > 0.f) ? scale : 1.f;

    uint32_t* qrow = reinterpret_cast<uint32_t*>(g_qx + (size_t)row * K_DIM);
#pragma unroll
    for (int i = 0; i < 4; ++i) {
        float f[4] = {v[i].x, v[i].y, v[i].z, v[i].w};
        uint32_t packed = 0;
#pragma unroll
        for (int j = 0; j < 4; ++j) {
            float q = rintf(f[j] / sdiv);            // IEEE div + rint-half-even == jnp
            q = fminf(fmaxf(q, -127.f), 127.f);
            packed |= ((uint32_t)(uint8_t)(int8_t)(int)q) << (8 * j);
        }
        qrow[t + i * 256] = packed;
    }
}

// ---------------------------------------------------------------------------
// GEMM helpers
// ---------------------------------------------------------------------------
__device__ __forceinline__ uint32_t smem_u32(const void* p) {
    return (uint32_t)__cvta_generic_to_shared(p);
}
__device__ __forceinline__ void cp_async16(uint32_t s, const void* g) {
    asm volatile("cp.async.cg.shared.global [%0], [%1], 16;\n" :: "r"(s), "l"(g));
}
__device__ __forceinline__ void cp_commit() {
    asm volatile("cp.async.commit_group;\n" ::: "memory");
}
__device__ __forceinline__ void mma_s8(int* c, const uint32_t* a, const uint32_t* b) {
    asm volatile(
        "mma.sync.aligned.m16n8k32.row.col.s32.s8.s8.s32 "
        "{%0,%1,%2,%3}, {%4,%5,%6,%7}, {%8,%9}, {%0,%1,%2,%3};\n"
        : "+r"(c[0]), "+r"(c[1]), "+r"(c[2]), "+r"(c[3])
        : "r"(a[0]), "r"(a[1]), "r"(a[2]), "r"(a[3]), "r"(b[0]), "r"(b[1]));
}

__device__ __forceinline__ void load_tile(int8_t* As, int8_t* Bs,
                                          const int8_t* Ag, const int8_t* Bg,
                                          int k0, int t) {
    // 128 rows x 64B per operand = 512 x 16B chunks; 256 threads -> 2 each
#pragma unroll
    for (int i = 0; i < 2; ++i) {
        int id  = t + i * 256;
        int row = id >> 2;
        int c   = (id & 3) << 4;
        cp_async16(smem_u32(As + row * SSTRIDE + c), Ag + (size_t)row * K_DIM + k0 + c);
        cp_async16(smem_u32(Bs + row * SSTRIDE + c), Bg + (size_t)row * K_DIM + k0 + c);
    }
}

// ---------------------------------------------------------------------------
// 128x128 CTA tile, 8 warps (4 M x 2 N), warp tile 32x64, m16n8k32 IMMA.
// cp.async double buffering over K (64 iters of BK=64).
// ---------------------------------------------------------------------------
__global__ void __launch_bounds__(256)
gemm_kernel(const float* __restrict__ wscale,
            const float* __restrict__ bias,
            float* __restrict__ out) {
    __shared__ int8_t As[2][BM * SSTRIDE];
    __shared__ int8_t Bs[2][BN * SSTRIDE];

    const int bn = blockIdx.x, bm = blockIdx.y;
    const int t = threadIdx.x;
    const int warp = t >> 5, lane = t & 31;
    const int wm = warp >> 1;   // 0..3 -> 32-row slice
    const int wn = warp & 1;    // 0..1 -> 64-col slice
    const int g   = lane >> 2;  // group id 0..7
    const int tig = lane & 3;   // thread-in-group

    const int8_t* Ag = g_qx + (size_t)(bm * BM) * K_DIM;
    const int8_t* Bg = g_w8 + (size_t)(bn * BN) * K_DIM;

    int acc[2][8][4];
#pragma unroll
    for (int mt = 0; mt < 2; ++mt)
#pragma unroll
        for (int nt = 0; nt < 8; ++nt)
#pragma unroll
            for (int r = 0; r < 4; ++r) acc[mt][nt][r] = 0;

    const int NIT = K_DIM / BK;   // 64
    load_tile(As[0], Bs[0], Ag, Bg, 0, t);  cp_commit();
    load_tile(As[1], Bs[1], Ag, Bg, BK, t); cp_commit();

    for (int j = 0; j < NIT; ++j) {
        if (j < NIT - 1) asm volatile("cp.async.wait_group 1;\n" ::: "memory");
        else             asm volatile("cp.async.wait_group 0;\n" ::: "memory");
        __syncthreads();

        const int buf = j & 1;
        const int8_t* Asb = As[buf];
        const int8_t* Bsb = Bs[buf];

#pragma unroll
        for (int ks = 0; ks < 2; ++ks) {
            const int kb = ks * 32;
            uint32_t afrag[2][4], bfrag[8][2];
#pragma unroll
            for (int mt = 0; mt < 2; ++mt) {
                const int8_t* base = Asb + (wm * 32 + mt * 16 + g) * SSTRIDE + kb + tig * 4;
                afrag[mt][0] = *(const uint32_t*)(base);
                afrag[mt][1] = *(const uint32_t*)(base + 8 * SSTRIDE);
                afrag[mt][2] = *(const uint32_t*)(base + 16);
                afrag[mt][3] = *(const uint32_t*)(base + 8 * SSTRIDE + 16);
            }
#pragma unroll
            for (int nt = 0; nt < 8; ++nt) {
                const int8_t* base = Bsb + (wn * 64 + nt * 8 + g) * SSTRIDE + kb + tig * 4;
                bfrag[nt][0] = *(const uint32_t*)(base);
                bfrag[nt][1] = *(const uint32_t*)(base + 16);
            }
#pragma unroll
            for (int mt = 0; mt < 2; ++mt)
#pragma unroll
                for (int nt = 0; nt < 8; ++nt)
                    mma_s8(acc[mt][nt], afrag[mt], bfrag[nt]);
        }
        __syncthreads();

        if (j + 2 < NIT) {
            load_tile(As[buf], Bs[buf], Ag, Bg, (j + 2) * BK, t);
            cp_commit();
        }
    }

    // Epilogue: y = (acc * wscale[n]) * xscale[m] + bias[n]
#pragma unroll
    for (int mt = 0; mt < 2; ++mt) {
#pragma unroll
        for (int r2 = 0; r2 < 2; ++r2) {
            const int m = bm * BM + wm * 32 + mt * 16 + r2 * 8 + g;
            const float xs = g_xscale[m];
            float* orow = out + (size_t)m * N_DIM;
#pragma unroll
            for (int nt = 0; nt < 8; ++nt) {
                const int n = bn * BN + wn * 64 + nt * 8 + tig * 2;
                const float ws0 = __ldg(&wscale[n]);
                const float ws1 = __ldg(&wscale[n + 1]);
                float v0 = ((float)acc[mt][nt][r2 * 2 + 0] * ws0) * xs + __ldg(&bias[n]);
                float v1 = ((float)acc[mt][nt][r2 * 2 + 1] * ws1) * xs + __ldg(&bias[n + 1]);
                *(float2*)&orow[n] = make_float2(v0, v1);
            }
        }
    }
}

// ---------------------------------------------------------------------------
extern "C" void kernel_launch(void* const* d_in, const int* in_sizes, int n_in,
                              void* d_out, int out_size) {
    const float* x      = (const float*)d_in[0];
    const void*  weight = d_in[1];
    const float* wscale = (const float*)d_in[2];
    const float* bias   = (const float*)d_in[3];
    float* out = (float*)d_out;

    const int T = in_sizes[0] / K_DIM;   // 8192

    detect_kernel<<<1, 32>>>((const int*)weight);
    pack_kernel<<<(N_DIM * K_DIM / 4) / 256, 256>>>(weight);
    quant_kernel<<<T, 256>>>(x);
    dim3 grid(N_DIM / BN, T / BM);
    gemm_kernel<<<grid, 256>>>(wscale, bias, out);
}

// round 9
// speedup vs baseline: 3.1614x; 3.1614x over previous
#include <cuda_runtime.h>
#include <cuda_bf16.h>
#include <cstdint>

// ---------------------------------------------------------------------------
// Int8Linear on GB300 (sm_103a). No tcgen05 kind::i8 on sm_103a -> exact int8
// math on the bf16 tensor pipe (ints <=127 exact in bf16, fp32 accum exact).
// R9: identical to R8 EXCEPT tcgen05.relinquish_alloc_permit is removed.
// The alloc/relinquish race (hi-wid-first arbiter issues warp3's relinquish
// before warp0's alloc -> illegal alloc -> trap) is the prime crash suspect;
// verified examples (test_mma.cu, test_2cta_mma_*) never relinquish.
// ---------------------------------------------------------------------------

#if defined(__CUDA_ARCH__) && (defined(__CUDA_ARCH_FEAT_SM103_ALL) || defined(__CUDA_ARCH_FEAT_SM100_ALL) || defined(__CUDA_ARCH_FEAT_SM101_ALL))
#define HAS_TC 1
#else
#define HAS_TC 0
#endif

#define K_DIM 4096
#define N_DIM 4096
#define MAX_T 8192

// ---- tcgen05 tile config ----
#define BM 128
#define BN 128
#define BK_EL 64              // bf16 K elements per stage (128B rows)
#define KSTEPS 4              // BK_EL / 16
#define NIT (K_DIM / BK_EL)   // 64

#define A_STAGE_BYTES (BM * 128)                       // 16384
#define B_STAGE_BYTES (BN * 128)                       // 16384
#define STAGE_BYTES   (A_STAGE_BYTES + B_STAGE_BYTES)  // 32768

#define OFF_TMEM   0u
#define OFF_BAR    16u
#define OFF_WS     1024u
#define OFF_BIAS   2048u
#define OFF_STAGE  4096u
#define SMEM_TOTAL (OFF_STAGE + 2 * STAGE_BYTES)       // 69632 -> 3 CTAs/SM

// ---- legacy IMMA tile config (compute_103 fallback cubin only) ----
#define LBM 128
#define LBN 128
#define LBK 64
#define SSTRIDE 80

// scratch (allocation-free rule: device globals)
__device__ __nv_bfloat16 g_qx[(size_t)MAX_T * K_DIM];
__device__ float         g_xscale[MAX_T];
__device__ __nv_bfloat16 g_wb[(size_t)N_DIM * K_DIM];
__device__ int8_t        g_w8[(size_t)N_DIM * K_DIM];
__device__ int8_t        g_qx8[(size_t)MAX_T * K_DIM];
__device__ int           g_w_is_int32;

// ---------------------------------------------------------------------------
__device__ __forceinline__ uint32_t smem_u32(const void* p) {
    return (uint32_t)__cvta_generic_to_shared(p);
}
__device__ __forceinline__ void cp_async16(uint32_t s, const void* g) {
    asm volatile("cp.async.cg.shared.global [%0], [%1], 16;\n" :: "r"(s), "l"(g));
}
__device__ __forceinline__ void cp_commit() {
    asm volatile("cp.async.commit_group;\n" ::: "memory");
}
__device__ __forceinline__ uint32_t pack_bf16x2(float a, float b) {
    __nv_bfloat162 h = __floats2bfloat162_rn(a, b);
    return *reinterpret_cast<uint32_t*>(&h);
}
__device__ __forceinline__ uint32_t elect_one() {
    uint32_t pred;
    asm volatile(
        "{\n\t.reg .pred p;\n\t"
        "elect.sync _|p, 0xFFFFFFFF;\n\t"
        "selp.b32 %0, 1, 0, p;\n\t}"
        : "=r"(pred));
    return pred;
}

// ---------------------------------------------------------------------------
__global__ void detect_kernel(const int* __restrict__ w) {
    if (threadIdx.x == 0 && blockIdx.x == 0) {
        int ok = 1;
#pragma unroll
        for (int i = 0; i < 64; ++i) {
            int v = w[i];
            if (v < -200 || v > 200) ok = 0;
        }
        g_w_is_int32 = ok;
    }
}

__global__ void pack_kernel(const void* __restrict__ w) {
    const size_t idx = (size_t)blockIdx.x * blockDim.x + threadIdx.x;
    float f0, f1, f2, f3;
    if (g_w_is_int32) {
        const int4 v = reinterpret_cast<const int4*>(w)[idx];
        f0 = (float)v.x; f1 = (float)v.y; f2 = (float)v.z; f3 = (float)v.w;
        uint32_t p = ((uint32_t)(uint8_t)(int8_t)v.x)
                   | ((uint32_t)(uint8_t)(int8_t)v.y << 8)
                   | ((uint32_t)(uint8_t)(int8_t)v.z << 16)
                   | ((uint32_t)(uint8_t)(int8_t)v.w << 24);
        reinterpret_cast<uint32_t*>(g_w8)[idx] = p;
    } else {
        const uint32_t p = reinterpret_cast<const uint32_t*>(w)[idx];
        f0 = (float)(int)(int8_t)(p & 0xff);
        f1 = (float)(int)(int8_t)((p >> 8) & 0xff);
        f2 = (float)(int)(int8_t)((p >> 16) & 0xff);
        f3 = (float)(int)(int8_t)(p >> 24);
        reinterpret_cast<uint32_t*>(g_w8)[idx] = p;
    }
    uint2 o;
    o.x = pack_bf16x2(f0, f1);
    o.y = pack_bf16x2(f2, f3);
    reinterpret_cast<uint2*>(g_wb)[idx] = o;
}

// ---------------------------------------------------------------------------
__global__ void quant_kernel(const float* __restrict__ x) {
    const int row = blockIdx.x;
    const int t   = threadIdx.x;
    const float* xr = x + (size_t)row * K_DIM;

    float4 v[4];
    float amax = 0.f;
#pragma unroll
    for (int i = 0; i < 4; ++i) {
        v[i] = reinterpret_cast<const float4*>(xr)[t + i * 256];
        amax = fmaxf(amax, fmaxf(fmaxf(fabsf(v[i].x), fabsf(v[i].y)),
                                 fmaxf(fabsf(v[i].z), fabsf(v[i].w))));
    }

    __shared__ float smax[8];
#pragma unroll
    for (int o = 16; o > 0; o >>= 1)
        amax = fmaxf(amax, __shfl_xor_sync(0xffffffffu, amax, o));
    if ((t & 31) == 0) smax[t >> 5] = amax;
    __syncthreads();
    if (t < 32) {
        float m = (t < 8) ? smax[t] : 0.f;
#pragma unroll
        for (int o = 4; o > 0; o >>= 1)
            m = fmaxf(m, __shfl_xor_sync(0xffffffffu, m, o));
        if (t == 0) smax[0] = m;
    }
    __syncthreads();

    const float scale = smax[0] / 127.0f;
    if (t == 0) g_xscale[row] = scale;
    const float sdiv = (scale > 0.f) ? scale : 1.f;

    uint2* qrow = reinterpret_cast<uint2*>(g_qx + (size_t)row * K_DIM);
#pragma unroll
    for (int i = 0; i < 4; ++i) {
        float f[4] = {v[i].x, v[i].y, v[i].z, v[i].w};
#pragma unroll
        for (int j = 0; j < 4; ++j) {
            float q = rintf(f[j] / sdiv);
            f[j] = fminf(fmaxf(q, -127.f), 127.f);
        }
        uint2 o;
        o.x = pack_bf16x2(f[0], f[1]);
        o.y = pack_bf16x2(f[2], f[3]);
        qrow[t + i * 256] = o;
    }
}

// ===========================================================================
// PATH 1: tcgen05 kind::f16 GEMM (sm_103a cubin)
// ===========================================================================
#if HAS_TC
__device__ __forceinline__ void mbar_init(uint32_t a, uint32_t cnt) {
    asm volatile("mbarrier.init.shared.b64 [%0], %1;" :: "r"(a), "r"(cnt) : "memory");
}
__device__ __forceinline__ void mbar_wait(uint32_t a, uint32_t parity) {
    asm volatile(
        "{\n\t.reg .pred P;\n\t"
        "W_%=:\n\t"
        "mbarrier.try_wait.parity.acquire.cta.shared::cta.b64 P, [%0], %1, 0x989680;\n\t"
        "@!P bra W_%=;\n\t}"
        :: "r"(a), "r"(parity) : "memory");
}
__device__ __forceinline__ void tc_commit(uint32_t bar) {
    asm volatile(
        "tcgen05.commit.cta_group::1.mbarrier::arrive::one.shared::cluster.b64 [%0];"
        :: "r"(bar) : "memory");
}
#define SW128(off) ((off) ^ (((off) >> 3) & 0x70))
__device__ __forceinline__ uint64_t make_desc_sw128(uint32_t base) {
    const uint64_t DESC_BASE =
        (uint64_t(2)  << 61) | (uint64_t(1) << 46) |
        (uint64_t(64) << 32) | (uint64_t(1) << 16);
    return DESC_BASE | ((uint64_t)(base >> 4) & 0x3FFF);
}
// verified kind::f16 idesc: F32@4, BF16@7, BF16@10, (N>>3)<<17, (M>>4)<<24
// (for M=128,N=32 this formula reproduces test_mma.cu's 0x8080490 exactly)
#define MMA_IDESC ((1u << 4) | (1u << 7) | (1u << 10) | ((BN >> 3) << 17) | ((BM >> 4) << 24))

__device__ __forceinline__ void mma_f16_ss(uint32_t d_tmem, uint64_t a_desc,
                                           uint64_t b_desc, uint32_t en) {
    asm volatile(
        "{\n\t.reg .pred p;\n\t"
        "setp.ne.u32 p, %5, 0;\n\t"
        "tcgen05.mma.cta_group::1.kind::f16 [%0], %1, %2, %3, {%4, %4, %4, %4}, p;\n\t}"
        :: "r"(d_tmem), "l"(a_desc), "l"(b_desc), "r"(MMA_IDESC), "r"(0u), "r"(en)
        : "memory");
}
#endif  // HAS_TC

#if HAS_TC
__global__ void __launch_bounds__(128) __cluster_dims__(1, 1, 1)
#else
__global__ void __launch_bounds__(128)
#endif
gemm_tc(const float* __restrict__ wscale,
        const float* __restrict__ bias,
        float* __restrict__ out) {
#if HAS_TC
    extern __shared__ char smem[];
    const uint32_t sb = smem_u32(smem);
    const int bn = blockIdx.x, bm = blockIdx.y;
    const int tid = threadIdx.x, wid = tid >> 5, lane = tid & 31;

    // Warp 0 allocs 128 TMEM cols. NO relinquish by other warps —
    // matches test_mma.cu / test_2cta_mma_bf16 exactly (relinquish before
    // the CTA's alloc is illegal and the arbiter is hi-wid-first).
    if (wid == 0) {
        asm volatile("tcgen05.alloc.cta_group::1.sync.aligned.shared::cta.b32 [%0], %1;"
                     :: "r"(sb + OFF_TMEM), "r"(128u) : "memory");
    }

    if (tid == 0) mbar_init(sb + OFF_BAR, 1);
    if (tid < BN) {
        const int n0 = bn * BN;
        ((float*)(smem + OFF_WS))[tid]   = wscale[n0 + tid];
        ((float*)(smem + OFF_BIAS))[tid] = bias[n0 + tid];
    }
    __syncthreads();

    uint32_t tmem;
    asm volatile("ld.shared.b32 %0, [%1];" : "=r"(tmem) : "r"(sb + OFF_TMEM));

    const __nv_bfloat16* Ag = g_qx + (size_t)(bm * BM) * K_DIM;
    const __nv_bfloat16* Bg = g_wb + (size_t)(bn * BN) * K_DIM;

    // stage loader: A 128 rows x 128B + B 128 rows x 128B, SW128, 16B cp.async
#define LOAD_STAGE(IT)                                                          \
    do {                                                                        \
        const uint32_t _abase = sb + OFF_STAGE + ((IT) & 1) * STAGE_BYTES;      \
        const uint32_t _bbase = _abase + A_STAGE_BYTES;                         \
        const int _k0 = (IT) * BK_EL;                                           \
        _Pragma("unroll")                                                       \
        for (int _i = 0; _i < 8; ++_i) {                                        \
            int _c = tid + _i * 128;                                            \
            int _r = _c >> 3, _ce = (_c & 7) << 3;                              \
            uint32_t _off = (uint32_t)(_r * 128 + _ce * 2);                     \
            cp_async16(_abase + SW128(_off),                                    \
                       Ag + (size_t)_r * K_DIM + _k0 + _ce);                    \
        }                                                                       \
        _Pragma("unroll")                                                       \
        for (int _i = 0; _i < 8; ++_i) {                                        \
            int _c = tid + _i * 128;                                            \
            int _r = _c >> 3, _ce = (_c & 7) << 3;                              \
            uint32_t _off = (uint32_t)(_r * 128 + _ce * 2);                     \
            cp_async16(_bbase + SW128(_off),                                    \
                       Bg + (size_t)_r * K_DIM + _k0 + _ce);                    \
        }                                                                       \
        cp_commit();                                                            \
    } while (0)

    LOAD_STAGE(0);

    for (int it = 0; it < NIT; ++it) {
        // prefetch next stage into the other buffer (freed by it-1's MMA wait)
        if (it + 1 < NIT) {
            LOAD_STAGE(it + 1);
            asm volatile("cp.async.wait_group 1;" ::: "memory");  // stage it resident
        } else {
            asm volatile("cp.async.wait_group 0;" ::: "memory");
        }
        __syncthreads();

        if (wid == 0) {
            asm volatile("fence.proxy.async.shared::cta;" ::: "memory");
            asm volatile("tcgen05.fence::after_thread_sync;" ::: "memory");
            if (elect_one()) {
                const uint32_t base = sb + OFF_STAGE + (it & 1) * STAGE_BYTES;
                const uint64_t ad = make_desc_sw128(base);
                const uint64_t bd = make_desc_sw128(base + A_STAGE_BYTES);
#pragma unroll
                for (int k = 0; k < KSTEPS; ++k)      // K=16 step -> +32B = +2 units
                    mma_f16_ss(tmem, ad + k * 2, bd + k * 2, (it > 0 || k > 0) ? 1u : 0u);
                tc_commit(sb + OFF_BAR);
            }
        }
        // synchronous: MMA of stage `it` fully complete before buffer reuse
        mbar_wait(sb + OFF_BAR, it & 1);
    }

    // ---- epilogue: fp32 TMEM -> dequant -> gmem ----
    asm volatile("tcgen05.fence::after_thread_sync;" ::: "memory");

    const int m = bm * BM + wid * 32 + lane;
    const float xs = g_xscale[m];
    float* orow = out + (size_t)m * N_DIM + bn * BN;
    const float* wsS = (const float*)(smem + OFF_WS);
    const float* bS  = (const float*)(smem + OFF_BIAS);

#pragma unroll
    for (int ch = 0; ch < BN / 32; ++ch) {
        uint32_t r[32];
        asm volatile(
            "tcgen05.ld.sync.aligned.32x32b.x32.b32 "
            "{%0, %1, %2, %3, %4, %5, %6, %7, "
            " %8, %9, %10, %11, %12, %13, %14, %15, "
            " %16, %17, %18, %19, %20, %21, %22, %23, "
            " %24, %25, %26, %27, %28, %29, %30, %31}, [%32];"
            : "=r"(r[0]),  "=r"(r[1]),  "=r"(r[2]),  "=r"(r[3]),
              "=r"(r[4]),  "=r"(r[5]),  "=r"(r[6]),  "=r"(r[7]),
              "=r"(r[8]),  "=r"(r[9]),  "=r"(r[10]), "=r"(r[11]),
              "=r"(r[12]), "=r"(r[13]), "=r"(r[14]), "=r"(r[15]),
              "=r"(r[16]), "=r"(r[17]), "=r"(r[18]), "=r"(r[19]),
              "=r"(r[20]), "=r"(r[21]), "=r"(r[22]), "=r"(r[23]),
              "=r"(r[24]), "=r"(r[25]), "=r"(r[26]), "=r"(r[27]),
              "=r"(r[28]), "=r"(r[29]), "=r"(r[30]), "=r"(r[31])
            : "r"(tmem + ch * 32));
        asm volatile("tcgen05.wait::ld.sync.aligned;" ::: "memory");

#pragma unroll
        for (int q = 0; q < 8; ++q) {
            const int c = ch * 32 + q * 4;
            float4 v;
            v.x = __uint_as_float(r[q * 4 + 0]) * wsS[c + 0] * xs + bS[c + 0];
            v.y = __uint_as_float(r[q * 4 + 1]) * wsS[c + 1] * xs + bS[c + 1];
            v.z = __uint_as_float(r[q * 4 + 2]) * wsS[c + 2] * xs + bS[c + 2];
            v.w = __uint_as_float(r[q * 4 + 3]) * wsS[c + 3] * xs + bS[c + 3];
            *reinterpret_cast<float4*>(orow + c) = v;
        }
    }

    __syncthreads();
    if (tid == 0)
        asm volatile("mbarrier.inval.shared.b64 [%0];" :: "r"(sb + OFF_BAR) : "memory");
    __syncthreads();
    if (wid == 0) {
        asm volatile("tcgen05.dealloc.cta_group::1.sync.aligned.b32 %0, %1;"
                     :: "r"(tmem), "r"(128u));
    }
#endif  // HAS_TC
}

// ===========================================================================
// PATH 2: legacy IMMA GEMM (compute_103 fallback cubin; empty on sm_103a)
// ===========================================================================
#if !HAS_TC && defined(__CUDA_ARCH__)
__device__ __forceinline__ void mma_s8(int* c, const uint32_t* a, const uint32_t* b) {
    asm volatile(
        "mma.sync.aligned.m16n8k32.row.col.s32.s8.s8.s32 "
        "{%0,%1,%2,%3}, {%4,%5,%6,%7}, {%8,%9}, {%0,%1,%2,%3};\n"
        : "+r"(c[0]), "+r"(c[1]), "+r"(c[2]), "+r"(c[3])
        : "r"(a[0]), "r"(a[1]), "r"(a[2]), "r"(a[3]), "r"(b[0]), "r"(b[1]));
}
#endif

__global__ void quant8_kernel() {
#if !HAS_TC && defined(__CUDA_ARCH__)
    const size_t idx = (size_t)blockIdx.x * blockDim.x + threadIdx.x;
    const uint2 p = reinterpret_cast<const uint2*>(g_qx)[idx];
    const __nv_bfloat162 h0 = *reinterpret_cast<const __nv_bfloat162*>(&p.x);
    const __nv_bfloat162 h1 = *reinterpret_cast<const __nv_bfloat162*>(&p.y);
    uint32_t o = ((uint32_t)(uint8_t)(int8_t)(int)__bfloat162float(h0.x))
               | ((uint32_t)(uint8_t)(int8_t)(int)__bfloat162float(h0.y) << 8)
               | ((uint32_t)(uint8_t)(int8_t)(int)__bfloat162float(h1.x) << 16)
               | ((uint32_t)(uint8_t)(int8_t)(int)__bfloat162float(h1.y) << 24);
    reinterpret_cast<uint32_t*>(g_qx8)[idx] = o;
#endif
}

__global__ void __launch_bounds__(256)
gemm_legacy(const float* __restrict__ wscale,
            const float* __restrict__ bias,
            float* __restrict__ out) {
#if !HAS_TC && defined(__CUDA_ARCH__)
    __shared__ int8_t As[2][LBM * SSTRIDE];
    __shared__ int8_t Bs[2][LBN * SSTRIDE];

    const int bn = blockIdx.x, bm = blockIdx.y;
    const int t = threadIdx.x;
    const int warp = t >> 5, lane = t & 31;
    const int wm = warp >> 1, wn = warp & 1;
    const int g = lane >> 2, tig = lane & 3;

    const int8_t* Ag = g_qx8 + (size_t)(bm * LBM) * K_DIM;
    const int8_t* Bg = g_w8  + (size_t)(bn * LBN) * K_DIM;

    int acc[2][8][4];
#pragma unroll
    for (int mt = 0; mt < 2; ++mt)
#pragma unroll
        for (int nt = 0; nt < 8; ++nt)
#pragma unroll
            for (int r = 0; r < 4; ++r) acc[mt][nt][r] = 0;

    const int NITL = K_DIM / LBK;
#define LOAD_L(J, BUF)                                                           \
    do {                                                                         \
        _Pragma("unroll")                                                        \
        for (int _i = 0; _i < 2; ++_i) {                                         \
            int _id = t + _i * 256;                                              \
            int _row = _id >> 2, _c = (_id & 3) << 4;                            \
            cp_async16(smem_u32(As[BUF] + _row * SSTRIDE + _c),                  \
                       Ag + (size_t)_row * K_DIM + (J) * LBK + _c);              \
            cp_async16(smem_u32(Bs[BUF] + _row * SSTRIDE + _c),                  \
                       Bg + (size_t)_row * K_DIM + (J) * LBK + _c);              \
        }                                                                        \
        cp_commit();                                                             \
    } while (0)

    LOAD_L(0, 0);
    LOAD_L(1, 1);

    for (int j = 0; j < NITL; ++j) {
        if (j < NITL - 1) asm volatile("cp.async.wait_group 1;\n" ::: "memory");
        else              asm volatile("cp.async.wait_group 0;\n" ::: "memory");
        __syncthreads();

        const int buf = j & 1;
        const int8_t* Asb = As[buf];
        const int8_t* Bsb = Bs[buf];

#pragma unroll
        for (int ks = 0; ks < 2; ++ks) {
            const int kb = ks * 32;
            uint32_t afrag[2][4], bfrag[8][2];
#pragma unroll
            for (int mt = 0; mt < 2; ++mt) {
                const int8_t* base = Asb + (wm * 32 + mt * 16 + g) * SSTRIDE + kb + tig * 4;
                afrag[mt][0] = *(const uint32_t*)(base);
                afrag[mt][1] = *(const uint32_t*)(base + 8 * SSTRIDE);
                afrag[mt][2] = *(const uint32_t*)(base + 16);
                afrag[mt][3] = *(const uint32_t*)(base + 8 * SSTRIDE + 16);
            }
#pragma unroll
            for (int nt = 0; nt < 8; ++nt) {
                const int8_t* base = Bsb + (wn * 64 + nt * 8 + g) * SSTRIDE + kb + tig * 4;
                bfrag[nt][0] = *(const uint32_t*)(base);
                bfrag[nt][1] = *(const uint32_t*)(base + 16);
            }
#pragma unroll
            for (int mt = 0; mt < 2; ++mt)
#pragma unroll
                for (int nt = 0; nt < 8; ++nt)
                    mma_s8(acc[mt][nt], afrag[mt], bfrag[nt]);
        }
        __syncthreads();

        if (j + 2 < NITL) LOAD_L(j + 2, buf);
    }

#pragma unroll
    for (int mt = 0; mt < 2; ++mt) {
#pragma unroll
        for (int r2 = 0; r2 < 2; ++r2) {
            const int m = bm * LBM + wm * 32 + mt * 16 + r2 * 8 + g;
            const float xs = g_xscale[m];
            float* orow = out + (size_t)m * N_DIM;
#pragma unroll
            for (int nt = 0; nt < 8; ++nt) {
                const int n = bn * LBN + wn * 64 + nt * 8 + tig * 2;
                float v0 = ((float)acc[mt][nt][r2 * 2 + 0] * __ldg(&wscale[n])) * xs + __ldg(&bias[n]);
                float v1 = ((float)acc[mt][nt][r2 * 2 + 1] * __ldg(&wscale[n + 1])) * xs + __ldg(&bias[n + 1]);
                *(float2*)&orow[n] = make_float2(v0, v1);
            }
        }
    }
#endif  // !HAS_TC
}

// ---------------------------------------------------------------------------
extern "C" void kernel_launch(void* const* d_in, const int* in_sizes, int n_in,
                              void* d_out, int out_size) {
    const float* x      = (const float*)d_in[0];
    const void*  weight = d_in[1];
    const float* wscale = (const float*)d_in[2];
    const float* bias   = (const float*)d_in[3];
    float* out = (float*)d_out;

    const int T = in_sizes[0] / K_DIM;   // 8192

    cudaFuncSetAttribute(gemm_tc, cudaFuncAttributeMaxDynamicSharedMemorySize,
                         SMEM_TOTAL);

    detect_kernel<<<1, 32>>>((const int*)weight);
    pack_kernel<<<(N_DIM * K_DIM / 4) / 256, 256>>>(weight);
    quant_kernel<<<T, 256>>>(x);
    quant8_kernel<<<((size_t)T * K_DIM / 4) / 256, 256>>>();   // empty on sm_103a

    // exactly one of these has a compiled body at runtime
    dim3 grid_tc(N_DIM / BN, T / BM);
    gemm_tc<<<grid_tc, 128, SMEM_TOTAL>>>(wscale, bias, out);
    dim3 grid_l(N_DIM / LBN, T / LBM);
    gemm_legacy<<<grid_l, 256>>>(wscale, bias, out);
}

// round 10
// speedup vs baseline: 3.4674x; 1.0968x over previous
#include <cuda_runtime.h>
#include <cuda_bf16.h>
#include <cstdint>

// ---------------------------------------------------------------------------
// Int8Linear on GB300 (sm_103a). No tcgen05 kind::i8 on sm_103a -> exact int8
// math on the bf16 tensor pipe (ints <=127 exact in bf16, fp32 accum exact).
// R10 (from first passing tcgen05 R9 @602us):
//   - lag-1 commit wait: MMA(it) overlaps stage-(it+1) cp.async loads
//   - removed dead quant8/legacy launches (22us of empty-launch overhead)
// ---------------------------------------------------------------------------

#if defined(__CUDA_ARCH__) && (defined(__CUDA_ARCH_FEAT_SM103_ALL) || defined(__CUDA_ARCH_FEAT_SM100_ALL) || defined(__CUDA_ARCH_FEAT_SM101_ALL))
#define HAS_TC 1
#else
#define HAS_TC 0
#endif

#define K_DIM 4096
#define N_DIM 4096
#define MAX_T 8192

#define BM 128
#define BN 128
#define BK_EL 64              // bf16 K elements per stage (128B rows)
#define KSTEPS 4              // BK_EL / 16
#define NIT (K_DIM / BK_EL)   // 64

#define A_STAGE_BYTES (BM * 128)                       // 16384
#define B_STAGE_BYTES (BN * 128)                       // 16384
#define STAGE_BYTES   (A_STAGE_BYTES + B_STAGE_BYTES)  // 32768

#define OFF_TMEM   0u
#define OFF_BAR    16u
#define OFF_WS     1024u
#define OFF_BIAS   2048u
#define OFF_STAGE  4096u
#define SMEM_TOTAL (OFF_STAGE + 2 * STAGE_BYTES)       // 69632 -> 3 CTAs/SM

// scratch (allocation-free rule: device globals)
__device__ __nv_bfloat16 g_qx[(size_t)MAX_T * K_DIM];
__device__ float         g_xscale[MAX_T];
__device__ __nv_bfloat16 g_wb[(size_t)N_DIM * K_DIM];
__device__ int           g_w_is_int32;

// ---------------------------------------------------------------------------
__device__ __forceinline__ uint32_t smem_u32(const void* p) {
    return (uint32_t)__cvta_generic_to_shared(p);
}
__device__ __forceinline__ void cp_async16(uint32_t s, const void* g) {
    asm volatile("cp.async.cg.shared.global [%0], [%1], 16;\n" :: "r"(s), "l"(g));
}
__device__ __forceinline__ void cp_commit() {
    asm volatile("cp.async.commit_group;\n" ::: "memory");
}
__device__ __forceinline__ uint32_t pack_bf16x2(float a, float b) {
    __nv_bfloat162 h = __floats2bfloat162_rn(a, b);
    return *reinterpret_cast<uint32_t*>(&h);
}
__device__ __forceinline__ uint32_t elect_one() {
    uint32_t pred;
    asm volatile(
        "{\n\t.reg .pred p;\n\t"
        "elect.sync _|p, 0xFFFFFFFF;\n\t"
        "selp.b32 %0, 1, 0, p;\n\t}"
        : "=r"(pred));
    return pred;
}

// ---------------------------------------------------------------------------
__global__ void detect_kernel(const int* __restrict__ w) {
    if (threadIdx.x == 0 && blockIdx.x == 0) {
        int ok = 1;
#pragma unroll
        for (int i = 0; i < 64; ++i) {
            int v = w[i];
            if (v < -200 || v > 200) ok = 0;
        }
        g_w_is_int32 = ok;
    }
}

__global__ void pack_kernel(const void* __restrict__ w) {
    const size_t idx = (size_t)blockIdx.x * blockDim.x + threadIdx.x;
    float f0, f1, f2, f3;
    if (g_w_is_int32) {
        const int4 v = reinterpret_cast<const int4*>(w)[idx];
        f0 = (float)v.x; f1 = (float)v.y; f2 = (float)v.z; f3 = (float)v.w;
    } else {
        const uint32_t p = reinterpret_cast<const uint32_t*>(w)[idx];
        f0 = (float)(int)(int8_t)(p & 0xff);
        f1 = (float)(int)(int8_t)((p >> 8) & 0xff);
        f2 = (float)(int)(int8_t)((p >> 16) & 0xff);
        f3 = (float)(int)(int8_t)(p >> 24);
    }
    uint2 o;
    o.x = pack_bf16x2(f0, f1);
    o.y = pack_bf16x2(f2, f3);
    reinterpret_cast<uint2*>(g_wb)[idx] = o;
}

// ---------------------------------------------------------------------------
__global__ void quant_kernel(const float* __restrict__ x) {
    const int row = blockIdx.x;
    const int t   = threadIdx.x;
    const float* xr = x + (size_t)row * K_DIM;

    float4 v[4];
    float amax = 0.f;
#pragma unroll
    for (int i = 0; i < 4; ++i) {
        v[i] = reinterpret_cast<const float4*>(xr)[t + i * 256];
        amax = fmaxf(amax, fmaxf(fmaxf(fabsf(v[i].x), fabsf(v[i].y)),
                                 fmaxf(fabsf(v[i].z), fabsf(v[i].w))));
    }

    __shared__ float smax[8];
#pragma unroll
    for (int o = 16; o > 0; o >>= 1)
        amax = fmaxf(amax, __shfl_xor_sync(0xffffffffu, amax, o));
    if ((t & 31) == 0) smax[t >> 5] = amax;
    __syncthreads();
    if (t < 32) {
        float m = (t < 8) ? smax[t] : 0.f;
#pragma unroll
        for (int o = 4; o > 0; o >>= 1)
            m = fmaxf(m, __shfl_xor_sync(0xffffffffu, m, o));
        if (t == 0) smax[0] = m;
    }
    __syncthreads();

    const float scale = smax[0] / 127.0f;
    if (t == 0) g_xscale[row] = scale;
    const float sdiv = (scale > 0.f) ? scale : 1.f;

    uint2* qrow = reinterpret_cast<uint2*>(g_qx + (size_t)row * K_DIM);
#pragma unroll
    for (int i = 0; i < 4; ++i) {
        float f[4] = {v[i].x, v[i].y, v[i].z, v[i].w};
#pragma unroll
        for (int j = 0; j < 4; ++j) {
            float q = rintf(f[j] / sdiv);
            f[j] = fminf(fmaxf(q, -127.f), 127.f);
        }
        uint2 o;
        o.x = pack_bf16x2(f[0], f[1]);
        o.y = pack_bf16x2(f[2], f[3]);
        qrow[t + i * 256] = o;
    }
}

// ===========================================================================
// tcgen05 kind::f16 GEMM (sm_103a cubin; empty body otherwise — sm_103a cubin
// is always selected at runtime on GB300, proven by R9)
// ===========================================================================
#if HAS_TC
__device__ __forceinline__ void mbar_init(uint32_t a, uint32_t cnt) {
    asm volatile("mbarrier.init.shared.b64 [%0], %1;" :: "r"(a), "r"(cnt) : "memory");
}
__device__ __forceinline__ void mbar_wait(uint32_t a, uint32_t parity) {
    asm volatile(
        "{\n\t.reg .pred P;\n\t"
        "W_%=:\n\t"
        "mbarrier.try_wait.parity.acquire.cta.shared::cta.b64 P, [%0], %1, 0x989680;\n\t"
        "@!P bra W_%=;\n\t}"
        :: "r"(a), "r"(parity) : "memory");
}
__device__ __forceinline__ void tc_commit(uint32_t bar) {
    asm volatile(
        "tcgen05.commit.cta_group::1.mbarrier::arrive::one.shared::cluster.b64 [%0];"
        :: "r"(bar) : "memory");
}
#define SW128(off) ((off) ^ (((off) >> 3) & 0x70))
__device__ __forceinline__ uint64_t make_desc_sw128(uint32_t base) {
    const uint64_t DESC_BASE =
        (uint64_t(2)  << 61) | (uint64_t(1) << 46) |
        (uint64_t(64) << 32) | (uint64_t(1) << 16);
    return DESC_BASE | ((uint64_t)(base >> 4) & 0x3FFF);
}
// verified kind::f16 idesc: F32@4, BF16@7, BF16@10, (N>>3)<<17, (M>>4)<<24
#define MMA_IDESC ((1u << 4) | (1u << 7) | (1u << 10) | ((BN >> 3) << 17) | ((BM >> 4) << 24))

__device__ __forceinline__ void mma_f16_ss(uint32_t d_tmem, uint64_t a_desc,
                                           uint64_t b_desc, uint32_t en) {
    asm volatile(
        "{\n\t.reg .pred p;\n\t"
        "setp.ne.u32 p, %5, 0;\n\t"
        "tcgen05.mma.cta_group::1.kind::f16 [%0], %1, %2, %3, {%4, %4, %4, %4}, p;\n\t}"
        :: "r"(d_tmem), "l"(a_desc), "l"(b_desc), "r"(MMA_IDESC), "r"(0u), "r"(en)
        : "memory");
}
#endif  // HAS_TC

#if HAS_TC
__global__ void __launch_bounds__(128) __cluster_dims__(1, 1, 1)
#else
__global__ void __launch_bounds__(128)
#endif
gemm_tc(const float* __restrict__ wscale,
        const float* __restrict__ bias,
        float* __restrict__ out) {
#if HAS_TC
    extern __shared__ char smem[];
    const uint32_t sb = smem_u32(smem);
    const int bn = blockIdx.x, bm = blockIdx.y;
    const int tid = threadIdx.x, wid = tid >> 5, lane = tid & 31;

    // Warp 0 allocs 128 TMEM cols; no relinquish (pre-alloc relinquish races
    // under the hi-wid-first arbiter and traps — R9's fix).
    if (wid == 0) {
        asm volatile("tcgen05.alloc.cta_group::1.sync.aligned.shared::cta.b32 [%0], %1;"
                     :: "r"(sb + OFF_TMEM), "r"(128u) : "memory");
    }

    if (tid == 0) mbar_init(sb + OFF_BAR, 1);
    if (tid < BN) {
        const int n0 = bn * BN;
        ((float*)(smem + OFF_WS))[tid]   = wscale[n0 + tid];
        ((float*)(smem + OFF_BIAS))[tid] = bias[n0 + tid];
    }
    __syncthreads();

    uint32_t tmem;
    asm volatile("ld.shared.b32 %0, [%1];" : "=r"(tmem) : "r"(sb + OFF_TMEM));

    const __nv_bfloat16* Ag = g_qx + (size_t)(bm * BM) * K_DIM;
    const __nv_bfloat16* Bg = g_wb + (size_t)(bn * BN) * K_DIM;

#define LOAD_STAGE(IT)                                                          \
    do {                                                                        \
        const uint32_t _abase = sb + OFF_STAGE + ((IT) & 1) * STAGE_BYTES;      \
        const uint32_t _bbase = _abase + A_STAGE_BYTES;                         \
        const int _k0 = (IT) * BK_EL;                                           \
        _Pragma("unroll")                                                       \
        for (int _i = 0; _i < 8; ++_i) {                                        \
            int _c = tid + _i * 128;                                            \
            int _r = _c >> 3, _ce = (_c & 7) << 3;                              \
            uint32_t _off = (uint32_t)(_r * 128 + _ce * 2);                     \
            cp_async16(_abase + SW128(_off),                                    \
                       Ag + (size_t)_r * K_DIM + _k0 + _ce);                    \
        }                                                                       \
        _Pragma("unroll")                                                       \
        for (int _i = 0; _i < 8; ++_i) {                                        \
            int _c = tid + _i * 128;                                            \
            int _r = _c >> 3, _ce = (_c & 7) << 3;                              \
            uint32_t _off = (uint32_t)(_r * 128 + _ce * 2);                     \
            cp_async16(_bbase + SW128(_off),                                    \
                       Bg + (size_t)_r * K_DIM + _k0 + _ce);                    \
        }                                                                       \
        cp_commit();                                                            \
    } while (0)

    LOAD_STAGE(0);

    for (int it = 0; it < NIT; ++it) {
        // lag-1 wait: MMA(it-1) must finish before stage it+1 overwrites its
        // buffer ((it+1)&1 == (it-1)&1). MMA(it-1) overlaps stage-it loads.
        if (it >= 1) mbar_wait(sb + OFF_BAR, (it - 1) & 1);

        if (it + 1 < NIT) {
            LOAD_STAGE(it + 1);
            asm volatile("cp.async.wait_group 1;" ::: "memory");  // stage it resident
        } else {
            asm volatile("cp.async.wait_group 0;" ::: "memory");
        }
        __syncthreads();

        if (wid == 0) {
            asm volatile("fence.proxy.async.shared::cta;" ::: "memory");
            asm volatile("tcgen05.fence::after_thread_sync;" ::: "memory");
            if (elect_one()) {
                const uint32_t base = sb + OFF_STAGE + (it & 1) * STAGE_BYTES;
                const uint64_t ad = make_desc_sw128(base);
                const uint64_t bd = make_desc_sw128(base + A_STAGE_BYTES);
#pragma unroll
                for (int k = 0; k < KSTEPS; ++k)      // K=16 step -> +32B = +2 units
                    mma_f16_ss(tmem, ad + k * 2, bd + k * 2, (it > 0 || k > 0) ? 1u : 0u);
                tc_commit(sb + OFF_BAR);
            }
        }
    }
    // final MMA completion
    mbar_wait(sb + OFF_BAR, (NIT - 1) & 1);

    // ---- epilogue: fp32 TMEM -> dequant -> gmem ----
    asm volatile("tcgen05.fence::after_thread_sync;" ::: "memory");

    const int m = bm * BM + wid * 32 + lane;
    const float xs = g_xscale[m];
    float* orow = out + (size_t)m * N_DIM + bn * BN;
    const float* wsS = (const float*)(smem + OFF_WS);
    const float* bS  = (const float*)(smem + OFF_BIAS);

#pragma unroll
    for (int ch = 0; ch < BN / 32; ++ch) {
        uint32_t r[32];
        asm volatile(
            "tcgen05.ld.sync.aligned.32x32b.x32.b32 "
            "{%0, %1, %2, %3, %4, %5, %6, %7, "
            " %8, %9, %10, %11, %12, %13, %14, %15, "
            " %16, %17, %18, %19, %20, %21, %22, %23, "
            " %24, %25, %26, %27, %28, %29, %30, %31}, [%32];"
            : "=r"(r[0]),  "=r"(r[1]),  "=r"(r[2]),  "=r"(r[3]),
              "=r"(r[4]),  "=r"(r[5]),  "=r"(r[6]),  "=r"(r[7]),
              "=r"(r[8]),  "=r"(r[9]),  "=r"(r[10]), "=r"(r[11]),
              "=r"(r[12]), "=r"(r[13]), "=r"(r[14]), "=r"(r[15]),
              "=r"(r[16]), "=r"(r[17]), "=r"(r[18]), "=r"(r[19]),
              "=r"(r[20]), "=r"(r[21]), "=r"(r[22]), "=r"(r[23]),
              "=r"(r[24]), "=r"(r[25]), "=r"(r[26]), "=r"(r[27]),
              "=r"(r[28]), "=r"(r[29]), "=r"(r[30]), "=r"(r[31])
            : "r"(tmem + ch * 32));
        asm volatile("tcgen05.wait::ld.sync.aligned;" ::: "memory");

#pragma unroll
        for (int q = 0; q < 8; ++q) {
            const int c = ch * 32 + q * 4;
            float4 v;
            v.x = __uint_as_float(r[q * 4 + 0]) * wsS[c + 0] * xs + bS[c + 0];
            v.y = __uint_as_float(r[q * 4 + 1]) * wsS[c + 1] * xs + bS[c + 1];
            v.z = __uint_as_float(r[q * 4 + 2]) * wsS[c + 2] * xs + bS[c + 2];
            v.w = __uint_as_float(r[q * 4 + 3]) * wsS[c + 3] * xs + bS[c + 3];
            *reinterpret_cast<float4*>(orow + c) = v;
        }
    }

    __syncthreads();
    if (tid == 0)
        asm volatile("mbarrier.inval.shared.b64 [%0];" :: "r"(sb + OFF_BAR) : "memory");
    __syncthreads();
    if (wid == 0) {
        asm volatile("tcgen05.dealloc.cta_group::1.sync.aligned.b32 %0, %1;"
                     :: "r"(tmem), "r"(128u));
    }
#endif  // HAS_TC
}

// ---------------------------------------------------------------------------
extern "C" void kernel_launch(void* const* d_in, const int* in_sizes, int n_in,
                              void* d_out, int out_size) {
    const float* x      = (const float*)d_in[0];
    const void*  weight = d_in[1];
    const float* wscale = (const float*)d_in[2];
    const float* bias   = (const float*)d_in[3];
    float* out = (float*)d_out;

    const int T = in_sizes[0] / K_DIM;   // 8192

    cudaFuncSetAttribute(gemm_tc, cudaFuncAttributeMaxDynamicSharedMemorySize,
                         SMEM_TOTAL);

    detect_kernel<<<1, 32>>>((const int*)weight);
    pack_kernel<<<(N_DIM * K_DIM / 4) / 256, 256>>>(weight);
    quant_kernel<<<T, 256>>>(x);

    dim3 grid_tc(N_DIM / BN, T / BM);
    gemm_tc<<<grid_tc, 128, SMEM_TOTAL>>>(wscale, bias, out);
}

// round 11
// speedup vs baseline: 5.3408x; 1.5403x over previous
#include <cuda_runtime.h>
#include <cuda_bf16.h>
#include <cstdint>

// ---------------------------------------------------------------------------
// Int8Linear on GB300 (sm_103a). Exact int8 math on bf16 tensor pipe.
// R11 (from R10 @549us, gemm 500us, latency-bound @ 1 CTA/SM):
//   - BN 128 -> 256 (halves B traffic, doubles tensor work per dispatch)
//   - 4-stage cp.async pipeline, prefetch distance 3, per-stage done-barriers
//     (R5's structure; crash-safe now that the relinquish race is removed)
// ---------------------------------------------------------------------------

#if defined(__CUDA_ARCH__) && (defined(__CUDA_ARCH_FEAT_SM103_ALL) || defined(__CUDA_ARCH_FEAT_SM100_ALL) || defined(__CUDA_ARCH_FEAT_SM101_ALL))
#define HAS_TC 1
#else
#define HAS_TC 0
#endif

#define K_DIM 4096
#define N_DIM 4096
#define MAX_T 8192

#define BM 128
#define BN 256
#define BK_EL 64              // bf16 K elements per stage (128B rows)
#define STAGES 4
#define KSTEPS 4              // BK_EL / 16
#define NIT (K_DIM / BK_EL)   // 64

#define A_STAGE_BYTES (BM * 128)                       // 16384
#define B_STAGE_BYTES (BN * 128)                       // 32768
#define STAGE_BYTES   (A_STAGE_BYTES + B_STAGE_BYTES)  // 49152

#define OFF_TMEM   0u
#define OFF_BAR    16u        // done[0..3] @ +16,+24,+32,+40
#define OFF_WS     1024u      // 256 floats
#define OFF_BIAS   2048u      // 256 floats
#define OFF_STAGE  4096u
#define SMEM_TOTAL (OFF_STAGE + STAGES * STAGE_BYTES)  // 200704

// scratch (allocation-free rule: device globals)
__device__ __nv_bfloat16 g_qx[(size_t)MAX_T * K_DIM];
__device__ float         g_xscale[MAX_T];
__device__ __nv_bfloat16 g_wb[(size_t)N_DIM * K_DIM];
__device__ int           g_w_is_int32;

// ---------------------------------------------------------------------------
__device__ __forceinline__ uint32_t smem_u32(const void* p) {
    return (uint32_t)__cvta_generic_to_shared(p);
}
__device__ __forceinline__ void cp_async16(uint32_t s, const void* g) {
    asm volatile("cp.async.cg.shared.global [%0], [%1], 16;\n" :: "r"(s), "l"(g));
}
__device__ __forceinline__ void cp_commit() {
    asm volatile("cp.async.commit_group;\n" ::: "memory");
}
__device__ __forceinline__ uint32_t pack_bf16x2(float a, float b) {
    __nv_bfloat162 h = __floats2bfloat162_rn(a, b);
    return *reinterpret_cast<uint32_t*>(&h);
}
__device__ __forceinline__ uint32_t elect_one() {
    uint32_t pred;
    asm volatile(
        "{\n\t.reg .pred p;\n\t"
        "elect.sync _|p, 0xFFFFFFFF;\n\t"
        "selp.b32 %0, 1, 0, p;\n\t}"
        : "=r"(pred));
    return pred;
}

// ---------------------------------------------------------------------------
__global__ void detect_kernel(const int* __restrict__ w) {
    if (threadIdx.x == 0 && blockIdx.x == 0) {
        int ok = 1;
#pragma unroll
        for (int i = 0; i < 64; ++i) {
            int v = w[i];
            if (v < -200 || v > 200) ok = 0;
        }
        g_w_is_int32 = ok;
    }
}

__global__ void pack_kernel(const void* __restrict__ w) {
    const size_t idx = (size_t)blockIdx.x * blockDim.x + threadIdx.x;
    float f0, f1, f2, f3;
    if (g_w_is_int32) {
        const int4 v = reinterpret_cast<const int4*>(w)[idx];
        f0 = (float)v.x; f1 = (float)v.y; f2 = (float)v.z; f3 = (float)v.w;
    } else {
        const uint32_t p = reinterpret_cast<const uint32_t*>(w)[idx];
        f0 = (float)(int)(int8_t)(p & 0xff);
        f1 = (float)(int)(int8_t)((p >> 8) & 0xff);
        f2 = (float)(int)(int8_t)((p >> 16) & 0xff);
        f3 = (float)(int)(int8_t)(p >> 24);
    }
    uint2 o;
    o.x = pack_bf16x2(f0, f1);
    o.y = pack_bf16x2(f2, f3);
    reinterpret_cast<uint2*>(g_wb)[idx] = o;
}

// ---------------------------------------------------------------------------
__global__ void quant_kernel(const float* __restrict__ x) {
    const int row = blockIdx.x;
    const int t   = threadIdx.x;
    const float* xr = x + (size_t)row * K_DIM;

    float4 v[4];
    float amax = 0.f;
#pragma unroll
    for (int i = 0; i < 4; ++i) {
        v[i] = reinterpret_cast<const float4*>(xr)[t + i * 256];
        amax = fmaxf(amax, fmaxf(fmaxf(fabsf(v[i].x), fabsf(v[i].y)),
                                 fmaxf(fabsf(v[i].z), fabsf(v[i].w))));
    }

    __shared__ float smax[8];
#pragma unroll
    for (int o = 16; o > 0; o >>= 1)
        amax = fmaxf(amax, __shfl_xor_sync(0xffffffffu, amax, o));
    if ((t & 31) == 0) smax[t >> 5] = amax;
    __syncthreads();
    if (t < 32) {
        float m = (t < 8) ? smax[t] : 0.f;
#pragma unroll
        for (int o = 4; o > 0; o >>= 1)
            m = fmaxf(m, __shfl_xor_sync(0xffffffffu, m, o));
        if (t == 0) smax[0] = m;
    }
    __syncthreads();

    const float scale = smax[0] / 127.0f;
    if (t == 0) g_xscale[row] = scale;
    const float sdiv = (scale > 0.f) ? scale : 1.f;

    uint2* qrow = reinterpret_cast<uint2*>(g_qx + (size_t)row * K_DIM);
#pragma unroll
    for (int i = 0; i < 4; ++i) {
        float f[4] = {v[i].x, v[i].y, v[i].z, v[i].w};
#pragma unroll
        for (int j = 0; j < 4; ++j) {
            float q = rintf(f[j] / sdiv);
            f[j] = fminf(fmaxf(q, -127.f), 127.f);
        }
        uint2 o;
        o.x = pack_bf16x2(f[0], f[1]);
        o.y = pack_bf16x2(f[2], f[3]);
        qrow[t + i * 256] = o;
    }
}

// ===========================================================================
// tcgen05 kind::f16 GEMM (sm_103a cubin)
// ===========================================================================
#if HAS_TC
__device__ __forceinline__ void mbar_init(uint32_t a, uint32_t cnt) {
    asm volatile("mbarrier.init.shared.b64 [%0], %1;" :: "r"(a), "r"(cnt) : "memory");
}
__device__ __forceinline__ void mbar_wait(uint32_t a, uint32_t parity) {
    asm volatile(
        "{\n\t.reg .pred P;\n\t"
        "W_%=:\n\t"
        "mbarrier.try_wait.parity.acquire.cta.shared::cta.b64 P, [%0], %1, 0x989680;\n\t"
        "@!P bra W_%=;\n\t}"
        :: "r"(a), "r"(parity) : "memory");
}
__device__ __forceinline__ void tc_commit(uint32_t bar) {
    asm volatile(
        "tcgen05.commit.cta_group::1.mbarrier::arrive::one.shared::cluster.b64 [%0];"
        :: "r"(bar) : "memory");
}
#define SW128(off) ((off) ^ (((off) >> 3) & 0x70))
__device__ __forceinline__ uint64_t make_desc_sw128(uint32_t base) {
    const uint64_t DESC_BASE =
        (uint64_t(2)  << 61) | (uint64_t(1) << 46) |
        (uint64_t(64) << 32) | (uint64_t(1) << 16);
    return DESC_BASE | ((uint64_t)(base >> 4) & 0x3FFF);
}
// kind::f16 idesc: F32@4, BF16@7, BF16@10, N-field [16:23) = N/4, (M>>4)<<24
#define MMA_IDESC ((1u << 4) | (1u << 7) | (1u << 10) | ((BN / 4) << 16) | ((BM >> 4) << 24))

__device__ __forceinline__ void mma_f16_ss(uint32_t d_tmem, uint64_t a_desc,
                                           uint64_t b_desc, uint32_t en) {
    asm volatile(
        "{\n\t.reg .pred p;\n\t"
        "setp.ne.u32 p, %5, 0;\n\t"
        "tcgen05.mma.cta_group::1.kind::f16 [%0], %1, %2, %3, {%4, %4, %4, %4}, p;\n\t}"
        :: "r"(d_tmem), "l"(a_desc), "l"(b_desc), "r"(MMA_IDESC), "r"(0u), "r"(en)
        : "memory");
}
#endif  // HAS_TC

#if HAS_TC
__global__ void __launch_bounds__(128) __cluster_dims__(1, 1, 1)
#else
__global__ void __launch_bounds__(128)
#endif
gemm_tc(const float* __restrict__ wscale,
        const float* __restrict__ bias,
        float* __restrict__ out) {
#if HAS_TC
    extern __shared__ char smem[];
    const uint32_t sb = smem_u32(smem);
    const int bn = blockIdx.x, bm = blockIdx.y;
    const int tid = threadIdx.x, wid = tid >> 5, lane = tid & 31;

    // Warp 0 allocs 256 TMEM cols; no relinquish (R9 fix).
    if (wid == 0) {
        asm volatile("tcgen05.alloc.cta_group::1.sync.aligned.shared::cta.b32 [%0], %1;"
                     :: "r"(sb + OFF_TMEM), "r"(256u) : "memory");
    }

    if (tid == 0) {
#pragma unroll
        for (int s = 0; s < STAGES; ++s) mbar_init(sb + OFF_BAR + 8 * s, 1);
    }
#pragma unroll
    for (int i = tid; i < BN; i += 128) {
        const int n0 = bn * BN;
        ((float*)(smem + OFF_WS))[i]   = wscale[n0 + i];
        ((float*)(smem + OFF_BIAS))[i] = bias[n0 + i];
    }
    __syncthreads();

    uint32_t tmem;
    asm volatile("ld.shared.b32 %0, [%1];" : "=r"(tmem) : "r"(sb + OFF_TMEM));

    const __nv_bfloat16* Ag = g_qx + (size_t)(bm * BM) * K_DIM;
    const __nv_bfloat16* Bg = g_wb + (size_t)(bn * BN) * K_DIM;

    // stage loader: A 128 rows x 128B + B 256 rows x 128B, SW128, 16B cp.async
#define LOAD_STAGE(IT)                                                          \
    do {                                                                        \
        const uint32_t _abase = sb + OFF_STAGE + ((IT) % STAGES) * STAGE_BYTES; \
        const uint32_t _bbase = _abase + A_STAGE_BYTES;                         \
        const int _k0 = (IT) * BK_EL;                                           \
        _Pragma("unroll")                                                       \
        for (int _i = 0; _i < 8; ++_i) {                                        \
            int _c = tid + _i * 128;                                            \
            int _r = _c >> 3, _ce = (_c & 7) << 3;                              \
            uint32_t _off = (uint32_t)(_r * 128 + _ce * 2);                     \
            cp_async16(_abase + SW128(_off),                                    \
                       Ag + (size_t)_r * K_DIM + _k0 + _ce);                    \
        }                                                                       \
        _Pragma("unroll")                                                       \
        for (int _i = 0; _i < 16; ++_i) {                                       \
            int _c = tid + _i * 128;                                            \
            int _r = _c >> 3, _ce = (_c & 7) << 3;                              \
            uint32_t _off = (uint32_t)(_r * 128 + _ce * 2);                     \
            cp_async16(_bbase + SW128(_off),                                    \
                       Bg + (size_t)_r * K_DIM + _k0 + _ce);                    \
        }                                                                       \
        cp_commit();                                                            \
    } while (0)

    LOAD_STAGE(0);
    LOAD_STAGE(1);
    LOAD_STAGE(2);

    for (int it = 0; it < NIT; ++it) {
        // prefetch stage it+3 into buffer (it+3)%4 = (it-1)%4; requires
        // MMA(it-1) done. Lag-1: MMA(it-1) had a full iteration to complete.
        const int pf = it + 3;
        if (pf < NIT) {
            if (it >= 1)
                mbar_wait(sb + OFF_BAR + 8 * ((it - 1) % STAGES),
                          ((it - 1) / STAGES) & 1);
            LOAD_STAGE(pf);
        }

        // stage it resident: allow up to 3 younger groups outstanding
        {
            const int rem = NIT - 1 - it;
            if      (rem >= 3) asm volatile("cp.async.wait_group 3;" ::: "memory");
            else if (rem == 2) asm volatile("cp.async.wait_group 2;" ::: "memory");
            else if (rem == 1) asm volatile("cp.async.wait_group 1;" ::: "memory");
            else               asm volatile("cp.async.wait_group 0;" ::: "memory");
        }
        __syncthreads();

        if (wid == 0) {
            asm volatile("fence.proxy.async.shared::cta;" ::: "memory");
            asm volatile("tcgen05.fence::after_thread_sync;" ::: "memory");
            if (elect_one()) {
                const uint32_t base = sb + OFF_STAGE + (it % STAGES) * STAGE_BYTES;
                const uint64_t ad = make_desc_sw128(base);
                const uint64_t bd = make_desc_sw128(base + A_STAGE_BYTES);
#pragma unroll
                for (int k = 0; k < KSTEPS; ++k)      // K=16 step -> +32B = +2 units
                    mma_f16_ss(tmem, ad + k * 2, bd + k * 2, (it > 0 || k > 0) ? 1u : 0u);
                tc_commit(sb + OFF_BAR + 8 * (it % STAGES));
            }
        }
    }
    // final MMA completion
    mbar_wait(sb + OFF_BAR + 8 * ((NIT - 1) % STAGES), ((NIT - 1) / STAGES) & 1);

    // ---- epilogue: fp32 TMEM -> dequant -> gmem ----
    asm volatile("tcgen05.fence::after_thread_sync;" ::: "memory");

    const int m = bm * BM + wid * 32 + lane;
    const float xs = g_xscale[m];
    float* orow = out + (size_t)m * N_DIM + bn * BN;
    const float* wsS = (const float*)(smem + OFF_WS);
    const float* bS  = (const float*)(smem + OFF_BIAS);

#pragma unroll
    for (int ch = 0; ch < BN / 32; ++ch) {
        uint32_t r[32];
        asm volatile(
            "tcgen05.ld.sync.aligned.32x32b.x32.b32 "
            "{%0, %1, %2, %3, %4, %5, %6, %7, "
            " %8, %9, %10, %11, %12, %13, %14, %15, "
            " %16, %17, %18, %19, %20, %21, %22, %23, "
            " %24, %25, %26, %27, %28, %29, %30, %31}, [%32];"
            : "=r"(r[0]),  "=r"(r[1]),  "=r"(r[2]),  "=r"(r[3]),
              "=r"(r[4]),  "=r"(r[5]),  "=r"(r[6]),  "=r"(r[7]),
              "=r"(r[8]),  "=r"(r[9]),  "=r"(r[10]), "=r"(r[11]),
              "=r"(r[12]), "=r"(r[13]), "=r"(r[14]), "=r"(r[15]),
              "=r"(r[16]), "=r"(r[17]), "=r"(r[18]), "=r"(r[19]),
              "=r"(r[20]), "=r"(r[21]), "=r"(r[22]), "=r"(r[23]),
              "=r"(r[24]), "=r"(r[25]), "=r"(r[26]), "=r"(r[27]),
              "=r"(r[28]), "=r"(r[29]), "=r"(r[30]), "=r"(r[31])
            : "r"(tmem + ch * 32));
        asm volatile("tcgen05.wait::ld.sync.aligned;" ::: "memory");

#pragma unroll
        for (int q = 0; q < 8; ++q) {
            const int c = ch * 32 + q * 4;
            float4 v;
            v.x = __uint_as_float(r[q * 4 + 0]) * wsS[c + 0] * xs + bS[c + 0];
            v.y = __uint_as_float(r[q * 4 + 1]) * wsS[c + 1] * xs + bS[c + 1];
            v.z = __uint_as_float(r[q * 4 + 2]) * wsS[c + 2] * xs + bS[c + 2];
            v.w = __uint_as_float(r[q * 4 + 3]) * wsS[c + 3] * xs + bS[c + 3];
            *reinterpret_cast<float4*>(orow + c) = v;
        }
    }

    __syncthreads();
    if (tid == 0) {
#pragma unroll
        for (int s = 0; s < STAGES; ++s)
            asm volatile("mbarrier.inval.shared.b64 [%0];"
                         :: "r"(sb + OFF_BAR + 8 * s) : "memory");
    }
    __syncthreads();
    if (wid == 0) {
        asm volatile("tcgen05.dealloc.cta_group::1.sync.aligned.b32 %0, %1;"
                     :: "r"(tmem), "r"(256u));
    }
#endif  // HAS_TC
}

// ---------------------------------------------------------------------------
extern "C" void kernel_launch(void* const* d_in, const int* in_sizes, int n_in,
                              void* d_out, int out_size) {
    const float* x      = (const float*)d_in[0];
    const void*  weight = d_in[1];
    const float* wscale = (const float*)d_in[2];
    const float* bias   = (const float*)d_in[3];
    float* out = (float*)d_out;

    const int T = in_sizes[0] / K_DIM;   // 8192

    cudaFuncSetAttribute(gemm_tc, cudaFuncAttributeMaxDynamicSharedMemorySize,
                         SMEM_TOTAL);

    detect_kernel<<<1, 32>>>((const int*)weight);
    pack_kernel<<<(N_DIM * K_DIM / 4) / 256, 256>>>(weight);
    quant_kernel<<<T, 256>>>(x);

    dim3 grid_tc(N_DIM / BN, T / BM);
    gemm_tc<<<grid_tc, 128, SMEM_TOTAL>>>(wscale, bias, out);
}

// round 12
// speedup vs baseline: 5.6235x; 1.0529x over previous
#include <cuda_runtime.h>
#include <cuda_bf16.h>
#include <cstdint>

// ---------------------------------------------------------------------------
// Int8Linear on GB300 (sm_103a). Exact int8 math on bf16 tensor pipe.
// R12 (from R11 @356us, gemm 306us, L2-traffic-bound at 3GB):
//   - BM 128 -> 256: two M=128 subtiles (D0/D1 in TMEM 0/256) share ONE B
//     tile -> B traffic halves, total L2->SMEM 3GB -> 2GB (-33%)
//   - 3-stage pipeline, prefetch distance 2, per-stage done barriers
// ---------------------------------------------------------------------------

#if defined(__CUDA_ARCH__) && (defined(__CUDA_ARCH_FEAT_SM103_ALL) || defined(__CUDA_ARCH_FEAT_SM100_ALL) || defined(__CUDA_ARCH_FEAT_SM101_ALL))
#define HAS_TC 1
#else
#define HAS_TC 0
#endif

#define K_DIM 4096
#define N_DIM 4096
#define MAX_T 8192

#define BM 256                // CTA M tile (2 x 128 subtiles)
#define SM_TILE 128           // MMA M per dispatch
#define BN 256
#define BK_EL 64              // bf16 K elements per stage (128B rows)
#define STAGES 3
#define KSTEPS 4              // BK_EL / 16
#define NIT (K_DIM / BK_EL)   // 64

#define A_SUB_BYTES (SM_TILE * 128)                    // 16384 per subtile
#define B_STAGE_BYTES (BN * 128)                       // 32768
#define STAGE_BYTES (2 * A_SUB_BYTES + B_STAGE_BYTES)  // 65536

#define OFF_TMEM   0u
#define OFF_BAR    16u        // done[0..2] @ +16,+24,+32
#define OFF_WS     1024u      // 256 floats
#define OFF_BIAS   2048u      // 256 floats
#define OFF_STAGE  4096u
#define SMEM_TOTAL (OFF_STAGE + STAGES * STAGE_BYTES)  // 200704

// scratch (allocation-free rule: device globals)
__device__ __nv_bfloat16 g_qx[(size_t)MAX_T * K_DIM];
__device__ float         g_xscale[MAX_T];
__device__ __nv_bfloat16 g_wb[(size_t)N_DIM * K_DIM];
__device__ int           g_w_is_int32;

// ---------------------------------------------------------------------------
__device__ __forceinline__ uint32_t smem_u32(const void* p) {
    return (uint32_t)__cvta_generic_to_shared(p);
}
__device__ __forceinline__ void cp_async16(uint32_t s, const void* g) {
    asm volatile("cp.async.cg.shared.global [%0], [%1], 16;\n" :: "r"(s), "l"(g));
}
__device__ __forceinline__ void cp_commit() {
    asm volatile("cp.async.commit_group;\n" ::: "memory");
}
__device__ __forceinline__ uint32_t pack_bf16x2(float a, float b) {
    __nv_bfloat162 h = __floats2bfloat162_rn(a, b);
    return *reinterpret_cast<uint32_t*>(&h);
}
__device__ __forceinline__ uint32_t elect_one() {
    uint32_t pred;
    asm volatile(
        "{\n\t.reg .pred p;\n\t"
        "elect.sync _|p, 0xFFFFFFFF;\n\t"
        "selp.b32 %0, 1, 0, p;\n\t}"
        : "=r"(pred));
    return pred;
}

// ---------------------------------------------------------------------------
__global__ void detect_kernel(const int* __restrict__ w) {
    if (threadIdx.x == 0 && blockIdx.x == 0) {
        int ok = 1;
#pragma unroll
        for (int i = 0; i < 64; ++i) {
            int v = w[i];
            if (v < -200 || v > 200) ok = 0;
        }
        g_w_is_int32 = ok;
    }
}

__global__ void pack_kernel(const void* __restrict__ w) {
    const size_t idx = (size_t)blockIdx.x * blockDim.x + threadIdx.x;
    float f0, f1, f2, f3;
    if (g_w_is_int32) {
        const int4 v = reinterpret_cast<const int4*>(w)[idx];
        f0 = (float)v.x; f1 = (float)v.y; f2 = (float)v.z; f3 = (float)v.w;
    } else {
        const uint32_t p = reinterpret_cast<const uint32_t*>(w)[idx];
        f0 = (float)(int)(int8_t)(p & 0xff);
        f1 = (float)(int)(int8_t)((p >> 8) & 0xff);
        f2 = (float)(int)(int8_t)((p >> 16) & 0xff);
        f3 = (float)(int)(int8_t)(p >> 24);
    }
    uint2 o;
    o.x = pack_bf16x2(f0, f1);
    o.y = pack_bf16x2(f2, f3);
    reinterpret_cast<uint2*>(g_wb)[idx] = o;
}

// ---------------------------------------------------------------------------
__global__ void quant_kernel(const float* __restrict__ x) {
    const int row = blockIdx.x;
    const int t   = threadIdx.x;
    const float* xr = x + (size_t)row * K_DIM;

    float4 v[4];
    float amax = 0.f;
#pragma unroll
    for (int i = 0; i < 4; ++i) {
        v[i] = reinterpret_cast<const float4*>(xr)[t + i * 256];
        amax = fmaxf(amax, fmaxf(fmaxf(fabsf(v[i].x), fabsf(v[i].y)),
                                 fmaxf(fabsf(v[i].z), fabsf(v[i].w))));
    }

    __shared__ float smax[8];
#pragma unroll
    for (int o = 16; o > 0; o >>= 1)
        amax = fmaxf(amax, __shfl_xor_sync(0xffffffffu, amax, o));
    if ((t & 31) == 0) smax[t >> 5] = amax;
    __syncthreads();
    if (t < 32) {
        float m = (t < 8) ? smax[t] : 0.f;
#pragma unroll
        for (int o = 4; o > 0; o >>= 1)
            m = fmaxf(m, __shfl_xor_sync(0xffffffffu, m, o));
        if (t == 0) smax[0] = m;
    }
    __syncthreads();

    const float scale = smax[0] / 127.0f;
    if (t == 0) g_xscale[row] = scale;
    const float sdiv = (scale > 0.f) ? scale : 1.f;

    uint2* qrow = reinterpret_cast<uint2*>(g_qx + (size_t)row * K_DIM);
#pragma unroll
    for (int i = 0; i < 4; ++i) {
        float f[4] = {v[i].x, v[i].y, v[i].z, v[i].w};
#pragma unroll
        for (int j = 0; j < 4; ++j) {
            float q = rintf(f[j] / sdiv);
            f[j] = fminf(fmaxf(q, -127.f), 127.f);
        }
        uint2 o;
        o.x = pack_bf16x2(f[0], f[1]);
        o.y = pack_bf16x2(f[2], f[3]);
        qrow[t + i * 256] = o;
    }
}

// ===========================================================================
// tcgen05 kind::f16 GEMM (sm_103a cubin)
// ===========================================================================
#if HAS_TC
__device__ __forceinline__ void mbar_init(uint32_t a, uint32_t cnt) {
    asm volatile("mbarrier.init.shared.b64 [%0], %1;" :: "r"(a), "r"(cnt) : "memory");
}
__device__ __forceinline__ void mbar_wait(uint32_t a, uint32_t parity) {
    asm volatile(
        "{\n\t.reg .pred P;\n\t"
        "W_%=:\n\t"
        "mbarrier.try_wait.parity.acquire.cta.shared::cta.b64 P, [%0], %1, 0x989680;\n\t"
        "@!P bra W_%=;\n\t}"
        :: "r"(a), "r"(parity) : "memory");
}
__device__ __forceinline__ void tc_commit(uint32_t bar) {
    asm volatile(
        "tcgen05.commit.cta_group::1.mbarrier::arrive::one.shared::cluster.b64 [%0];"
        :: "r"(bar) : "memory");
}
#define SW128(off) ((off) ^ (((off) >> 3) & 0x70))
__device__ __forceinline__ uint64_t make_desc_sw128(uint32_t base) {
    const uint64_t DESC_BASE =
        (uint64_t(2)  << 61) | (uint64_t(1) << 46) |
        (uint64_t(64) << 32) | (uint64_t(1) << 16);
    return DESC_BASE | ((uint64_t)(base >> 4) & 0x3FFF);
}
// kind::f16 idesc: F32@4, BF16@7, BF16@10, N-field [16:23)=N/4, M-field=(M>>4)<<24
#define MMA_IDESC ((1u << 4) | (1u << 7) | (1u << 10) | ((BN / 4) << 16) | ((SM_TILE >> 4) << 24))

__device__ __forceinline__ void mma_f16_ss(uint32_t d_tmem, uint64_t a_desc,
                                           uint64_t b_desc, uint32_t en) {
    asm volatile(
        "{\n\t.reg .pred p;\n\t"
        "setp.ne.u32 p, %5, 0;\n\t"
        "tcgen05.mma.cta_group::1.kind::f16 [%0], %1, %2, %3, {%4, %4, %4, %4}, p;\n\t}"
        :: "r"(d_tmem), "l"(a_desc), "l"(b_desc), "r"(MMA_IDESC), "r"(0u), "r"(en)
        : "memory");
}
#endif  // HAS_TC

#if HAS_TC
__global__ void __launch_bounds__(128) __cluster_dims__(1, 1, 1)
#else
__global__ void __launch_bounds__(128)
#endif
gemm_tc(const float* __restrict__ wscale,
        const float* __restrict__ bias,
        float* __restrict__ out) {
#if HAS_TC
    extern __shared__ char smem[];
    const uint32_t sb = smem_u32(smem);
    const int bn = blockIdx.x, bm = blockIdx.y;
    const int tid = threadIdx.x, wid = tid >> 5, lane = tid & 31;

    // Warp 0 allocs 512 TMEM cols (D0 @ 0, D1 @ 256); no relinquish (R9 fix).
    if (wid == 0) {
        asm volatile("tcgen05.alloc.cta_group::1.sync.aligned.shared::cta.b32 [%0], %1;"
                     :: "r"(sb + OFF_TMEM), "r"(512u) : "memory");
    }

    if (tid == 0) {
#pragma unroll
        for (int s = 0; s < STAGES; ++s) mbar_init(sb + OFF_BAR + 8 * s, 1);
    }
#pragma unroll
    for (int i = tid; i < BN; i += 128) {
        const int n0 = bn * BN;
        ((float*)(smem + OFF_WS))[i]   = wscale[n0 + i];
        ((float*)(smem + OFF_BIAS))[i] = bias[n0 + i];
    }
    __syncthreads();

    uint32_t tmem;
    asm volatile("ld.shared.b32 %0, [%1];" : "=r"(tmem) : "r"(sb + OFF_TMEM));

    const __nv_bfloat16* Ag = g_qx + (size_t)(bm * BM) * K_DIM;       // 256 rows
    const __nv_bfloat16* Bg = g_wb + (size_t)(bn * BN) * K_DIM;

    // stage layout: [A0 16K][A1 16K][B 32K]; SW128 swizzled 128B rows
#define LOAD_STAGE(IT)                                                          \
    do {                                                                        \
        const uint32_t _base = sb + OFF_STAGE + ((IT) % STAGES) * STAGE_BYTES;  \
        const int _k0 = (IT) * BK_EL;                                           \
        _Pragma("unroll")                                                       \
        for (int _i = 0; _i < 16; ++_i) {  /* A: 256 rows in 2 subtiles */      \
            int _c = tid + _i * 128;                                            \
            int _r = _c >> 3, _ce = (_c & 7) << 3;                              \
            uint32_t _sub = (_r >= SM_TILE) ? 1u : 0u;                          \
            uint32_t _lr = _r & (SM_TILE - 1);                                  \
            uint32_t _off = (uint32_t)(_lr * 128 + _ce * 2);                    \
            cp_async16(_base + _sub * A_SUB_BYTES + SW128(_off),                \
                       Ag + (size_t)_r * K_DIM + _k0 + _ce);                    \
        }                                                                       \
        _Pragma("unroll")                                                       \
        for (int _i = 0; _i < 16; ++_i) {  /* B: 256 rows */                    \
            int _c = tid + _i * 128;                                            \
            int _r = _c >> 3, _ce = (_c & 7) << 3;                              \
            uint32_t _off = (uint32_t)(_r * 128 + _ce * 2);                     \
            cp_async16(_base + 2 * A_SUB_BYTES + SW128(_off),                   \
                       Bg + (size_t)_r * K_DIM + _k0 + _ce);                    \
        }                                                                       \
        cp_commit();                                                            \
    } while (0)

    LOAD_STAGE(0);
    LOAD_STAGE(1);

    for (int it = 0; it < NIT; ++it) {
        // prefetch stage it+2 into buffer (it+2)%3 = (it-1)%3: needs MMA(it-1)
        const int pf = it + 2;
        if (pf < NIT) {
            if (it >= 1)
                mbar_wait(sb + OFF_BAR + 8 * ((it - 1) % STAGES),
                          ((it - 1) / STAGES) & 1);
            LOAD_STAGE(pf);
        }

        {
            const int rem = NIT - 1 - it;
            if      (rem >= 2) asm volatile("cp.async.wait_group 2;" ::: "memory");
            else if (rem == 1) asm volatile("cp.async.wait_group 1;" ::: "memory");
            else               asm volatile("cp.async.wait_group 0;" ::: "memory");
        }
        __syncthreads();

        if (wid == 0) {
            asm volatile("fence.proxy.async.shared::cta;" ::: "memory");
            asm volatile("tcgen05.fence::after_thread_sync;" ::: "memory");
            if (elect_one()) {
                const uint32_t base = sb + OFF_STAGE + (it % STAGES) * STAGE_BYTES;
                const uint64_t a0d = make_desc_sw128(base);
                const uint64_t a1d = make_desc_sw128(base + A_SUB_BYTES);
                const uint64_t bd  = make_desc_sw128(base + 2 * A_SUB_BYTES);
                const uint32_t en0 = (it > 0) ? 1u : 0u;
#pragma unroll
                for (int k = 0; k < KSTEPS; ++k) {    // K=16 step -> +2 desc units
                    const uint32_t en = (k > 0) ? 1u : en0;
                    mma_f16_ss(tmem,       a0d + k * 2, bd + k * 2, en);
                    mma_f16_ss(tmem + 256, a1d + k * 2, bd + k * 2, en);
                }
                tc_commit(sb + OFF_BAR + 8 * (it % STAGES));
            }
        }
    }
    // final MMA completion: it=NIT-1 on barrier (NIT-1)%3
    mbar_wait(sb + OFF_BAR + 8 * ((NIT - 1) % STAGES), ((NIT - 1) / STAGES) & 1);

    // ---- epilogue: fp32 TMEM (2 subtiles) -> dequant -> gmem ----
    asm volatile("tcgen05.fence::after_thread_sync;" ::: "memory");

    const float* wsS = (const float*)(smem + OFF_WS);
    const float* bS  = (const float*)(smem + OFF_BIAS);

#pragma unroll
    for (int sub = 0; sub < 2; ++sub) {
        const int m = bm * BM + sub * SM_TILE + wid * 32 + lane;
        const float xs = g_xscale[m];
        float* orow = out + (size_t)m * N_DIM + bn * BN;
        const uint32_t dbase = tmem + sub * 256;

#pragma unroll
        for (int ch = 0; ch < BN / 32; ++ch) {
            uint32_t r[32];
            asm volatile(
                "tcgen05.ld.sync.aligned.32x32b.x32.b32 "
                "{%0, %1, %2, %3, %4, %5, %6, %7, "
                " %8, %9, %10, %11, %12, %13, %14, %15, "
                " %16, %17, %18, %19, %20, %21, %22, %23, "
                " %24, %25, %26, %27, %28, %29, %30, %31}, [%32];"
                : "=r"(r[0]),  "=r"(r[1]),  "=r"(r[2]),  "=r"(r[3]),
                  "=r"(r[4]),  "=r"(r[5]),  "=r"(r[6]),  "=r"(r[7]),
                  "=r"(r[8]),  "=r"(r[9]),  "=r"(r[10]), "=r"(r[11]),
                  "=r"(r[12]), "=r"(r[13]), "=r"(r[14]), "=r"(r[15]),
                  "=r"(r[16]), "=r"(r[17]), "=r"(r[18]), "=r"(r[19]),
                  "=r"(r[20]), "=r"(r[21]), "=r"(r[22]), "=r"(r[23]),
                  "=r"(r[24]), "=r"(r[25]), "=r"(r[26]), "=r"(r[27]),
                  "=r"(r[28]), "=r"(r[29]), "=r"(r[30]), "=r"(r[31])
                : "r"(dbase + ch * 32));
            asm volatile("tcgen05.wait::ld.sync.aligned;" ::: "memory");

#pragma unroll
            for (int q = 0; q < 8; ++q) {
                const int c = ch * 32 + q * 4;
                float4 v;
                v.x = __uint_as_float(r[q * 4 + 0]) * wsS[c + 0] * xs + bS[c + 0];
                v.y = __uint_as_float(r[q * 4 + 1]) * wsS[c + 1] * xs + bS[c + 1];
                v.z = __uint_as_float(r[q * 4 + 2]) * wsS[c + 2] * xs + bS[c + 2];
                v.w = __uint_as_float(r[q * 4 + 3]) * wsS[c + 3] * xs + bS[c + 3];
                *reinterpret_cast<float4*>(orow + c) = v;
            }
        }
    }

    __syncthreads();
    if (tid == 0) {
#pragma unroll
        for (int s = 0; s < STAGES; ++s)
            asm volatile("mbarrier.inval.shared.b64 [%0];"
                         :: "r"(sb + OFF_BAR + 8 * s) : "memory");
    }
    __syncthreads();
    if (wid == 0) {
        asm volatile("tcgen05.dealloc.cta_group::1.sync.aligned.b32 %0, %1;"
                     :: "r"(tmem), "r"(512u));
    }
#endif  // HAS_TC
}

// ---------------------------------------------------------------------------
extern "C" void kernel_launch(void* const* d_in, const int* in_sizes, int n_in,
                              void* d_out, int out_size) {
    const float* x      = (const float*)d_in[0];
    const void*  weight = d_in[1];
    const float* wscale = (const float*)d_in[2];
    const float* bias   = (const float*)d_in[3];
    float* out = (float*)d_out;

    const int T = in_sizes[0] / K_DIM;   // 8192

    cudaFuncSetAttribute(gemm_tc, cudaFuncAttributeMaxDynamicSharedMemorySize,
                         SMEM_TOTAL);

    detect_kernel<<<1, 32>>>((const int*)weight);
    pack_kernel<<<(N_DIM * K_DIM / 4) / 256, 256>>>(weight);
    quant_kernel<<<T, 256>>>(x);

    dim3 grid_tc(N_DIM / BN, T / BM);   // (16, 32) = 512 CTAs
    gemm_tc<<<grid_tc, 128, SMEM_TOTAL>>>(wscale, bias, out);
}